// round 5
// baseline (speedup 1.0000x reference)
#include <cuda_runtime.h>
#include <stdint.h>

// BFP quantizer: x (64, 256, 56, 56) fp32 NCHW, tile=8 along C (axis 1).
// bitwidth=16 -> m=7, qmax=127, step=2^(shared_exp-6).
// shared_exp = floor(log2(max(|x| over tile), eps)), eps=2^-23.
//
// R5: persistent grid-stride kernel. grid = 148 SMs * 6 CTAs of 256 threads
// = exactly one resident wave; each thread loops over ~7 work items with
// stride = total threads. Removes ~6 wave transitions + tail ramp-down of
// the flat 3136-CTA launch. Per-iteration access shape identical to the
// proven dense form: 8 front-batched streaming LDG.128 per item, warp lanes
// at consecutive 16B.

#define N_DIM   64
#define C_DIM   256
#define HW_DIM  3136               // 56*56
#define TILE_C  8
#define NTILES  (C_DIM / TILE_C)   // 32
#define HW4     (HW_DIM / 4)       // 784
#define TOTAL_ITEMS (N_DIM * NTILES * HW4)   // 1,605,632
#define EPS_F   1.1920928955078125e-07f      // 2^-23

#define SMS      148
#define CTAS_SM  6
#define BLOCK    256
#define GRID     (SMS * CTAS_SM)             // 888 CTAs, one wave

__global__ __launch_bounds__(BLOCK)
void bfp_quant_kernel(const float4* __restrict__ in, float4* __restrict__ out)
{
    const int stride = GRID * BLOCK;         // 227,328

    for (int t = blockIdx.x * BLOCK + threadIdx.x; t < TOTAL_ITEMS; t += stride) {
        int w4   = t % HW4;
        int rest = t / HW4;
        int ct   = rest % NTILES;
        int n    = rest / NTILES;

        long base = (long)n * (C_DIM * HW4) + (long)ct * (TILE_C * HW4) + w4;

        // Front-batched: 8 streaming LDG.128, dense across the warp
        float a[TILE_C][4];
        #pragma unroll
        for (int k = 0; k < TILE_C; k++) {
            float4 v = __ldcs(&in[base + (long)k * HW4]);
            a[k][0] = v.x; a[k][1] = v.y; a[k][2] = v.z; a[k][3] = v.w;
        }

        #pragma unroll
        for (int j = 0; j < 4; j++) {
            // tile max(|x|) clamped by eps
            float mx = EPS_F;
            #pragma unroll
            for (int k = 0; k < TILE_C; k++)
                mx = fmaxf(mx, fabsf(a[k][j]));

            // shared_exp = floor(log2(mx)): exponent bits (mx normal, >0)
            int e = (int)(__float_as_uint(mx) >> 23) - 127;

            // inv_step = 2^(6-e), step = 2^(e-6), both always normal
            float inv_step = __uint_as_float((uint32_t)(133 - e) << 23);
            float step     = __uint_as_float((uint32_t)(e + 121) << 23);

            #pragma unroll
            for (int k = 0; k < TILE_C; k++) {
                float q = rintf(a[k][j] * inv_step);   // round-half-to-even
                q = fminf(fmaxf(q, -127.0f), 127.0f);  // clamp +/-(2^7 - 1)
                a[k][j] = q * step;
            }
        }

        #pragma unroll
        for (int k = 0; k < TILE_C; k++) {
            float4 v;
            v.x = a[k][0]; v.y = a[k][1]; v.z = a[k][2]; v.w = a[k][3];
            __stcs(&out[base + (long)k * HW4], v);
        }
    }
}

extern "C" void kernel_launch(void* const* d_in, const int* in_sizes, int n_in,
                              void* d_out, int out_size)
{
    const float4* in  = (const float4*)d_in[0];
    float4*       out = (float4*)d_out;

    bfp_quant_kernel<<<GRID, BLOCK>>>(in, out);
}

// round 6
// speedup vs baseline: 1.0715x; 1.0715x over previous
#include <cuda_runtime.h>
#include <stdint.h>

// BFP quantizer: x (64, 256, 56, 56) fp32 NCHW, tile=8 along C (axis 1).
// bitwidth=16 -> m=7, qmax=127, step=2^(shared_exp-6).
// shared_exp = floor(log2(max(|x| over tile), eps)), eps=2^-23.
//
// R6 = exact revert to R2, the empirical best (kernel 56.96us, DRAM 79.0%).
// Sweep results: dense warp requests are mandatory (R3 strided: -36%);
// occupancy 20-60%, MLP 8-16, block 256/512, persistence all neutral ->
// ~79% of HBM spec is the mixed r/w stream ceiling for this access shape.
//
// Thread = (n, c_tile, w), covers float4 positions w and w+392 across all
// 8 channels of the tile: 16 front-batched streaming LDG.128, each with
// warp lanes at consecutive 16B (fully dense wavefronts).

#define N_DIM   64
#define C_DIM   256
#define HW_DIM  3136               // 56*56
#define TILE_C  8
#define NTILES  (C_DIM / TILE_C)   // 32
#define HW4     (HW_DIM / 4)       // 784
#define HW8     (HW4 / 2)          // 392
#define EPS_F   1.1920928955078125e-07f  // 2^-23

__global__ __launch_bounds__(256, 2)
void bfp_quant_kernel(const float4* __restrict__ in, float4* __restrict__ out)
{
    int t = blockIdx.x * blockDim.x + threadIdx.x;
    // t in [0, N*NTILES*HW8)
    int w    = t % HW8;
    int rest = t / HW8;
    int ct   = rest % NTILES;
    int n    = rest / NTILES;

    long base = (long)n * (C_DIM * HW4) + (long)ct * (TILE_C * HW4) + w;

    // Front-batched: 16 streaming LDG.128
    float a[TILE_C][2][4];
    #pragma unroll
    for (int k = 0; k < TILE_C; k++) {
        float4 v0 = __ldcs(&in[base + (long)k * HW4]);
        float4 v1 = __ldcs(&in[base + (long)k * HW4 + HW8]);
        a[k][0][0] = v0.x; a[k][0][1] = v0.y; a[k][0][2] = v0.z; a[k][0][3] = v0.w;
        a[k][1][0] = v1.x; a[k][1][1] = v1.y; a[k][1][2] = v1.z; a[k][1][3] = v1.w;
    }

    #pragma unroll
    for (int g = 0; g < 2; g++) {
        #pragma unroll
        for (int j = 0; j < 4; j++) {
            // tile max(|x|) clamped by eps
            float mx = EPS_F;
            #pragma unroll
            for (int k = 0; k < TILE_C; k++)
                mx = fmaxf(mx, fabsf(a[k][g][j]));

            // shared_exp = floor(log2(mx)): exponent bits (mx normal, >0)
            int e = (int)(__float_as_uint(mx) >> 23) - 127;

            // inv_step = 2^(6-e), step = 2^(e-6), both always normal
            float inv_step = __uint_as_float((uint32_t)(133 - e) << 23);
            float step     = __uint_as_float((uint32_t)(e + 121) << 23);

            #pragma unroll
            for (int k = 0; k < TILE_C; k++) {
                float q = rintf(a[k][g][j] * inv_step);   // round-half-even
                q = fminf(fmaxf(q, -127.0f), 127.0f);
                a[k][g][j] = q * step;
            }
        }
    }

    #pragma unroll
    for (int k = 0; k < TILE_C; k++) {
        float4 v0, v1;
        v0.x = a[k][0][0]; v0.y = a[k][0][1]; v0.z = a[k][0][2]; v0.w = a[k][0][3];
        v1.x = a[k][1][0]; v1.y = a[k][1][1]; v1.z = a[k][1][2]; v1.w = a[k][1][3];
        __stcs(&out[base + (long)k * HW4], v0);
        __stcs(&out[base + (long)k * HW4 + HW8], v1);
    }
}

extern "C" void kernel_launch(void* const* d_in, const int* in_sizes, int n_in,
                              void* d_out, int out_size)
{
    const float4* in  = (const float4*)d_in[0];
    float4*       out = (float4*)d_out;

    const int total_threads = N_DIM * NTILES * HW8;   // 802,816
    const int block = 256;
    const int grid  = total_threads / block;          // 3136 exactly

    bfp_quant_kernel<<<grid, block>>>(in, out);
}